// round 1
// baseline (speedup 1.0000x reference)
#include <cuda_runtime.h>
#include <math_constants.h>

// SpatialAttention: out = x * hardsigmoid(conv3x3([mean_c(x); max_c(x)]))
// x: [16, 256, 128, 128] fp32, conv_w: [1, 2, 3, 3] fp32.
//
// Strategy: chunk batches (4 at a time, 64 MiB x-slice fits L2) so the
// elementwise multiply re-reads x from L2 instead of DRAM.
//   k1 reduce : channel mean+max  (reads x from DRAM, warms L2)
//   k2 conv   : 3x3 conv + hardsigmoid on tiny 2-ch map
//   k3 mul    : out = x * att     (x from L2, out streamed to DRAM)

#define BATCH 16
#define CH    256
#define HH    128
#define WW    128
#define HWSZ  (HH * WW)        // 16384
#define HW4   (HWSZ / 4)       // 4096 float4 columns per (b,c) plane
#define CHUNK 4                // batches per chunk

__device__ float g_avg[BATCH * HWSZ];
__device__ float g_max[BATCH * HWSZ];
__device__ float g_att[BATCH * HWSZ];

// ---------------------------------------------------------------------------
// k1: per-(b,h,w) mean and max over 256 channels. float4 across W.
// grid: CHUNK*HW4 threads. Channel stride between loads = HWSZ floats (64KB),
// loads are independent -> unroll for MLP.
// ---------------------------------------------------------------------------
__global__ void __launch_bounds__(64) reduce_kernel(const float* __restrict__ x, int b0) {
    int t   = blockIdx.x * blockDim.x + threadIdx.x;   // 0 .. CHUNK*HW4-1
    int bl  = t >> 12;                                  // t / 4096
    int col = t & (HW4 - 1);                            // float4 column in plane
    int b   = b0 + bl;

    const float4* xp = reinterpret_cast<const float4*>(x) + (size_t)b * CH * HW4 + col;

    float4 s = make_float4(0.f, 0.f, 0.f, 0.f);
    float4 m = make_float4(-CUDART_INF_F, -CUDART_INF_F, -CUDART_INF_F, -CUDART_INF_F);

    #pragma unroll 16
    for (int c = 0; c < CH; c++) {
        float4 v = __ldg(xp + c * HW4);
        s.x += v.x; s.y += v.y; s.z += v.z; s.w += v.w;
        m.x = fmaxf(m.x, v.x); m.y = fmaxf(m.y, v.y);
        m.z = fmaxf(m.z, v.z); m.w = fmaxf(m.w, v.w);
    }

    const float inv = 1.0f / (float)CH;
    float4 a = make_float4(s.x * inv, s.y * inv, s.z * inv, s.w * inv);

    reinterpret_cast<float4*>(g_avg)[b * HW4 + col] = a;
    reinterpret_cast<float4*>(g_max)[b * HW4 + col] = m;
}

// ---------------------------------------------------------------------------
// k2: 3x3 conv (in=2: [avg, max]) with zero padding + hardsigmoid -> g_att.
// conv_w layout [1,2,3,3]: wt[in*9 + kh*3 + kw].
// ---------------------------------------------------------------------------
__global__ void __launch_bounds__(256) conv_kernel(const float* __restrict__ wt, int b0) {
    int t  = blockIdx.x * blockDim.x + threadIdx.x;    // 0 .. CHUNK*HWSZ-1
    int bl = t >> 14;                                   // t / 16384
    int hw = t & (HWSZ - 1);
    int h  = hw >> 7;
    int w  = hw & (WW - 1);
    int b  = b0 + bl;

    const float* __restrict__ A = g_avg + b * HWSZ;
    const float* __restrict__ M = g_max + b * HWSZ;

    float acc = 0.f;
    #pragma unroll
    for (int kh = 0; kh < 3; kh++) {
        int hh = h + kh - 1;
        if (hh < 0 || hh >= HH) continue;
        #pragma unroll
        for (int kw = 0; kw < 3; kw++) {
            int ww = w + kw - 1;
            if (ww < 0 || ww >= WW) continue;
            int o = hh * WW + ww;
            acc += __ldg(&wt[kh * 3 + kw])     * A[o]
                 + __ldg(&wt[9 + kh * 3 + kw]) * M[o];
        }
    }
    // hardsigmoid: clip(acc + 3, 0, 6) / 6
    float y = fminf(fmaxf(acc + 3.0f, 0.0f), 6.0f) * (1.0f / 6.0f);
    g_att[b * HWSZ + hw] = y;
}

// ---------------------------------------------------------------------------
// k3: out = x * att, float4 streaming. att float4 per 4 consecutive W.
// ---------------------------------------------------------------------------
__global__ void __launch_bounds__(256) mul_kernel(const float* __restrict__ x,
                                                  float* __restrict__ out, int b0) {
    int t   = blockIdx.x * blockDim.x + threadIdx.x;   // 0 .. CHUNK*CH*HW4-1
    int bl  = t >> 20;                                  // t / (CH*HW4) = t / 2^20
    int rem = t & ((CH * HW4) - 1);
    int col = rem & (HW4 - 1);
    int b   = b0 + bl;

    size_t idx = (size_t)b * CH * HW4 + rem;

    float4 v = reinterpret_cast<const float4*>(x)[idx];
    float4 a = __ldg(reinterpret_cast<const float4*>(g_att) + b * HW4 + col);

    v.x *= a.x; v.y *= a.y; v.z *= a.z; v.w *= a.w;
    reinterpret_cast<float4*>(out)[idx] = v;
}

extern "C" void kernel_launch(void* const* d_in, const int* in_sizes, int n_in,
                              void* d_out, int out_size) {
    const float* x  = (const float*)d_in[0];
    const float* wt = (const float*)d_in[1];
    float* out      = (float*)d_out;

    for (int b0 = 0; b0 < BATCH; b0 += CHUNK) {
        // 1) channel mean/max over the chunk (warms L2 with x-slice)
        reduce_kernel<<<(CHUNK * HW4) / 64, 64>>>(x, b0);
        // 2) tiny conv + hardsigmoid -> attention map
        conv_kernel<<<(CHUNK * HWSZ) / 256, 256>>>(wt, b0);
        // 3) elementwise multiply (x from L2, out to DRAM)
        mul_kernel<<<(CHUNK * CH * HW4) / 256, 256>>>(x, out, b0);
    }
}

// round 2
// speedup vs baseline: 1.6873x; 1.6873x over previous
#include <cuda_runtime.h>
#include <math_constants.h>

// SpatialAttention: out = x * hardsigmoid(conv3x3([mean_c(x); max_c(x)]))
// x: [16, 256, 128, 128] fp32, conv_w: [1, 2, 3, 3] fp32.
//
// Per 4-batch chunk (64 MiB, fits L2):
//   k1 reduce_part : channel-split (8 segs x 32 ch) partial sum/max -> scratch
//   k2 combine     : fold 8 partials -> g_avg (mean), g_max
//   k3 conv        : 3x3 conv + hardsigmoid -> g_att
//   k4 mul         : out = x * att (x from L2, out streamed w/ __stcs)

#define BATCH 16
#define CH    256
#define HH    128
#define WW    128
#define HWSZ  (HH * WW)        // 16384
#define HW4   (HWSZ / 4)       // 4096 float4 columns per (b,c) plane
#define CHUNK 4                // batches per chunk
#define SEG   8                // channel segments
#define CPS   (CH / SEG)       // 32 channels per segment

__device__ float g_pavg[SEG * CHUNK * HWSZ];   // partial sums
__device__ float g_pmax[SEG * CHUNK * HWSZ];   // partial maxes
__device__ float g_avg[BATCH * HWSZ];
__device__ float g_max[BATCH * HWSZ];
__device__ float g_att[BATCH * HWSZ];

// ---------------------------------------------------------------------------
// k1: partial channel reduce. Each thread: one float4 column, 32 channels.
// 131072 threads/chunk -> ~28 warps/SM, unroll-8 MLP.
// ---------------------------------------------------------------------------
__global__ void __launch_bounds__(256) reduce_part_kernel(const float* __restrict__ x, int b0) {
    int t    = blockIdx.x * blockDim.x + threadIdx.x;  // 0 .. SEG*CHUNK*HW4-1
    int col  = t & (HW4 - 1);
    int rest = t >> 12;                                 // seg*CHUNK + bl
    int bl   = rest & (CHUNK - 1);
    int seg  = rest >> 2;                               // rest / CHUNK
    int b    = b0 + bl;

    const float4* xp = reinterpret_cast<const float4*>(x)
                     + (size_t)b * CH * HW4 + (size_t)seg * CPS * HW4 + col;

    float4 s = make_float4(0.f, 0.f, 0.f, 0.f);
    float4 m = make_float4(-CUDART_INF_F, -CUDART_INF_F, -CUDART_INF_F, -CUDART_INF_F);

    #pragma unroll 8
    for (int c = 0; c < CPS; c++) {
        float4 v = xp[c * HW4];
        s.x += v.x; s.y += v.y; s.z += v.z; s.w += v.w;
        m.x = fmaxf(m.x, v.x); m.y = fmaxf(m.y, v.y);
        m.z = fmaxf(m.z, v.z); m.w = fmaxf(m.w, v.w);
    }

    reinterpret_cast<float4*>(g_pavg)[rest * HW4 + col] = s;
    reinterpret_cast<float4*>(g_pmax)[rest * HW4 + col] = m;
}

// ---------------------------------------------------------------------------
// k2: fold SEG partials -> mean / max per (b,h,w).
// ---------------------------------------------------------------------------
__global__ void __launch_bounds__(256) combine_kernel(int b0) {
    int t   = blockIdx.x * blockDim.x + threadIdx.x;   // 0 .. CHUNK*HW4-1
    int col = t & (HW4 - 1);
    int bl  = t >> 12;
    int b   = b0 + bl;

    float4 s = make_float4(0.f, 0.f, 0.f, 0.f);
    float4 m = make_float4(-CUDART_INF_F, -CUDART_INF_F, -CUDART_INF_F, -CUDART_INF_F);

    #pragma unroll
    for (int seg = 0; seg < SEG; seg++) {
        int rest = seg * CHUNK + bl;
        float4 ps = reinterpret_cast<const float4*>(g_pavg)[rest * HW4 + col];
        float4 pm = reinterpret_cast<const float4*>(g_pmax)[rest * HW4 + col];
        s.x += ps.x; s.y += ps.y; s.z += ps.z; s.w += ps.w;
        m.x = fmaxf(m.x, pm.x); m.y = fmaxf(m.y, pm.y);
        m.z = fmaxf(m.z, pm.z); m.w = fmaxf(m.w, pm.w);
    }

    const float inv = 1.0f / (float)CH;
    float4 a = make_float4(s.x * inv, s.y * inv, s.z * inv, s.w * inv);

    reinterpret_cast<float4*>(g_avg)[b * HW4 + col] = a;
    reinterpret_cast<float4*>(g_max)[b * HW4 + col] = m;
}

// ---------------------------------------------------------------------------
// k3: 3x3 conv (in=2: [avg, max]) with zero padding + hardsigmoid -> g_att.
// ---------------------------------------------------------------------------
__global__ void __launch_bounds__(256) conv_kernel(const float* __restrict__ wt, int b0) {
    int t  = blockIdx.x * blockDim.x + threadIdx.x;    // 0 .. CHUNK*HWSZ-1
    int bl = t >> 14;
    int hw = t & (HWSZ - 1);
    int h  = hw >> 7;
    int w  = hw & (WW - 1);
    int b  = b0 + bl;

    const float* __restrict__ A = g_avg + b * HWSZ;
    const float* __restrict__ M = g_max + b * HWSZ;

    float acc = 0.f;
    #pragma unroll
    for (int kh = 0; kh < 3; kh++) {
        int hh = h + kh - 1;
        if (hh < 0 || hh >= HH) continue;
        #pragma unroll
        for (int kw = 0; kw < 3; kw++) {
            int ww = w + kw - 1;
            if (ww < 0 || ww >= WW) continue;
            int o = hh * WW + ww;
            acc += __ldg(&wt[kh * 3 + kw])     * A[o]
                 + __ldg(&wt[9 + kh * 3 + kw]) * M[o];
        }
    }
    float y = fminf(fmaxf(acc + 3.0f, 0.0f), 6.0f) * (1.0f / 6.0f);
    g_att[b * HWSZ + hw] = y;
}

// ---------------------------------------------------------------------------
// k4: out = x * att. x hits L2 (warmed by k1); out streamed (evict-first).
// ---------------------------------------------------------------------------
__global__ void __launch_bounds__(256) mul_kernel(const float* __restrict__ x,
                                                  float* __restrict__ out, int b0) {
    int t   = blockIdx.x * blockDim.x + threadIdx.x;   // 0 .. CHUNK*CH*HW4-1
    int bl  = t >> 20;
    int rem = t & ((CH * HW4) - 1);
    int col = rem & (HW4 - 1);
    int b   = b0 + bl;

    size_t idx = ((size_t)b0 * CH * HW4) + ((size_t)bl << 20) + rem;
    (void)idx;
    size_t gidx = (size_t)b * CH * HW4 + rem;

    float4 v = reinterpret_cast<const float4*>(x)[gidx];
    float4 a = __ldg(reinterpret_cast<const float4*>(g_att) + b * HW4 + col);

    v.x *= a.x; v.y *= a.y; v.z *= a.z; v.w *= a.w;
    __stcs(reinterpret_cast<float4*>(out) + gidx, v);
}

extern "C" void kernel_launch(void* const* d_in, const int* in_sizes, int n_in,
                              void* d_out, int out_size) {
    const float* x  = (const float*)d_in[0];
    const float* wt = (const float*)d_in[1];
    float* out      = (float*)d_out;

    for (int b0 = 0; b0 < BATCH; b0 += CHUNK) {
        reduce_part_kernel<<<(SEG * CHUNK * HW4) / 256, 256>>>(x, b0);
        combine_kernel<<<(CHUNK * HW4) / 256, 256>>>(b0);
        conv_kernel<<<(CHUNK * HWSZ) / 256, 256>>>(wt, b0);
        mul_kernel<<<(CHUNK * CH * HW4) / 256, 256>>>(x, out, b0);
    }
}

// round 3
// speedup vs baseline: 1.7548x; 1.0400x over previous
#include <cuda_runtime.h>
#include <math_constants.h>

// SpatialAttention: out = x * hardsigmoid(conv3x3([mean_c(x); max_c(x)]))
// x: [16, 256, 128, 128] fp32, conv_w: [1, 2, 3, 3] fp32.
//
// Single fused kernel, software-pipelined across 2-batch chunks:
//   launch i:  reduce(chunk i)  |  conv(chunk i-1)  |  mul(chunk i-2)
// as disjoint blockIdx ranges. Steady state overlaps the DRAM read stream
// (reduce) with the DRAM write stream (mul), and mul's x reads hit L2
// (x slice loaded 2 launches earlier, ~96 MiB live < 126 MB L2).

#define BATCH 16
#define CH    256
#define HH    128
#define WW    128
#define HWSZ  (HH * WW)          // 16384
#define HW4   (HWSZ / 4)         // 4096 float4 cols per (b,c) plane
#define CHUNK 2                  // batches per chunk (32 MiB x-slice)
#define NCHNK (BATCH / CHUNK)    // 8 chunks
#define CPS   32                 // channels per channel-group (256/8)

#define COLS_PER_BLK 32
#define R_BLK (CHUNK * HW4 / COLS_PER_BLK)   // 256 reduce blocks
#define C_BLK (CHUNK * HWSZ / 256)           // 128 conv blocks
#define M_BLK (CHUNK * CH * HW4 / 256)       // 8192 mul blocks

__device__ float g_avg[BATCH * HWSZ];
__device__ float g_max[BATCH * HWSZ];
__device__ float g_att[BATCH * HWSZ];

__global__ void __launch_bounds__(256, 6)
fused_kernel(const float* __restrict__ x, const float* __restrict__ wt,
             float* __restrict__ out, int b_red, int b_conv, int b_mul) {
    __shared__ float4 ssum[256];
    __shared__ float4 smax[256];

    int bid = blockIdx.x;

    if (bid < R_BLK) {
        // ---------------- reduce phase: chunk b_red ----------------
        if (b_red < 0) return;
        int bl      = bid >> 7;            // / (HW4/COLS_PER_BLK = 128)
        int colBase = (bid & 127) * COLS_PER_BLK;
        int t     = threadIdx.x;
        int col_l = t & (COLS_PER_BLK - 1);
        int cg    = t >> 5;                // 0..7 channel group
        int b     = b_red + bl;

        const float4* xp = reinterpret_cast<const float4*>(x)
                         + (size_t)b * CH * HW4 + (size_t)cg * CPS * HW4
                         + colBase + col_l;

        float4 s = make_float4(0.f, 0.f, 0.f, 0.f);
        float4 m = make_float4(-CUDART_INF_F, -CUDART_INF_F, -CUDART_INF_F, -CUDART_INF_F);

        #pragma unroll 4
        for (int c = 0; c < CPS; c++) {
            float4 v = xp[c * HW4];
            s.x += v.x; s.y += v.y; s.z += v.z; s.w += v.w;
            m.x = fmaxf(m.x, v.x); m.y = fmaxf(m.y, v.y);
            m.z = fmaxf(m.z, v.z); m.w = fmaxf(m.w, v.w);
        }
        ssum[t] = s; smax[t] = m;
        __syncthreads();

        #pragma unroll
        for (int off = 128; off >= 32; off >>= 1) {
            if (t < off) {
                float4 s2 = ssum[t + off], m2 = smax[t + off];
                float4 sa = ssum[t],       ma = smax[t];
                sa.x += s2.x; sa.y += s2.y; sa.z += s2.z; sa.w += s2.w;
                ma.x = fmaxf(ma.x, m2.x); ma.y = fmaxf(ma.y, m2.y);
                ma.z = fmaxf(ma.z, m2.z); ma.w = fmaxf(ma.w, m2.w);
                ssum[t] = sa; smax[t] = ma;
            }
            __syncthreads();
        }

        if (t < COLS_PER_BLK) {
            const float inv = 1.0f / (float)CH;
            float4 sa = ssum[t], ma = smax[t];
            float4 a = make_float4(sa.x * inv, sa.y * inv, sa.z * inv, sa.w * inv);
            reinterpret_cast<float4*>(g_avg)[b * HW4 + colBase + t] = a;
            reinterpret_cast<float4*>(g_max)[b * HW4 + colBase + t] = ma;
        }
    } else if (bid < R_BLK + C_BLK) {
        // ---------------- conv phase: chunk b_conv ----------------
        if (b_conv < 0) return;
        int t  = (bid - R_BLK) * 256 + threadIdx.x;   // 0 .. CHUNK*HWSZ-1
        int bl = t >> 14;
        int hw = t & (HWSZ - 1);
        int h  = hw >> 7;
        int w  = hw & (WW - 1);
        int b  = b_conv + bl;

        const float* __restrict__ A = g_avg + b * HWSZ;
        const float* __restrict__ M = g_max + b * HWSZ;

        float acc = 0.f;
        #pragma unroll
        for (int kh = 0; kh < 3; kh++) {
            int hh = h + kh - 1;
            if (hh < 0 || hh >= HH) continue;
            #pragma unroll
            for (int kw = 0; kw < 3; kw++) {
                int ww = w + kw - 1;
                if (ww < 0 || ww >= WW) continue;
                int o = hh * WW + ww;
                acc += __ldg(&wt[kh * 3 + kw])     * A[o]
                     + __ldg(&wt[9 + kh * 3 + kw]) * M[o];
            }
        }
        float y = fminf(fmaxf(acc + 3.0f, 0.0f), 6.0f) * (1.0f / 6.0f);
        g_att[b * HWSZ + hw] = y;
    } else {
        // ---------------- mul phase: chunk b_mul ----------------
        if (b_mul < 0) return;
        int t   = (bid - R_BLK - C_BLK) * 256 + threadIdx.x; // 0..CHUNK*CH*HW4-1
        int bl  = t >> 20;                                    // / (CH*HW4)
        int rem = t & ((CH * HW4) - 1);
        int col = rem & (HW4 - 1);
        int b   = b_mul + bl;

        size_t gidx = (size_t)b * CH * HW4 + rem;

        float4 v = reinterpret_cast<const float4*>(x)[gidx];
        float4 a = __ldg(reinterpret_cast<const float4*>(g_att) + b * HW4 + col);

        v.x *= a.x; v.y *= a.y; v.z *= a.z; v.w *= a.w;
        __stcs(reinterpret_cast<float4*>(out) + gidx, v);
    }
}

extern "C" void kernel_launch(void* const* d_in, const int* in_sizes, int n_in,
                              void* d_out, int out_size) {
    const float* x  = (const float*)d_in[0];
    const float* wt = (const float*)d_in[1];
    float* out      = (float*)d_out;

    const int GRID = R_BLK + C_BLK + M_BLK;   // 8576 blocks

    for (int i = 0; i < NCHNK + 2; i++) {
        int br = (i < NCHNK)              ? i * CHUNK       : -1;
        int bc = (i >= 1 && i <= NCHNK)   ? (i - 1) * CHUNK : -1;
        int bm = (i >= 2)                 ? (i - 2) * CHUNK : -1;
        fused_kernel<<<GRID, 256>>>(x, wt, out, br, bc, bm);
    }
}